// round 3
// baseline (speedup 1.0000x reference)
#include <cuda_runtime.h>
#include <cuda_bf16.h>
#include <cstdint>

#define GLYPH_DIM 4096
#define PAD_IDX   4096
#define EMB_DIM   20
#define HIDDEN    32
#define MAX_LEN   64
#define HW        1659        // 21 * 79
#define WPB       4           // warps (samples) per block

// ---------------------------------------------------------------------------
// Device scratch
// ---------------------------------------------------------------------------
__device__ float g_utab[(GLYPH_DIM + 1) * HIDDEN];

// ---------------------------------------------------------------------------
// K0: u_table[g][i] = W_ih[i] . emb[g] + b_ih[i] + b_hh[i]   (4097 x 32)
// ---------------------------------------------------------------------------
__global__ void utab_kernel(const float* __restrict__ emb,
                            const float* __restrict__ W_ih,
                            const float* __restrict__ b_ih,
                            const float* __restrict__ b_hh)
{
    int warp = (blockIdx.x * blockDim.x + threadIdx.x) >> 5;
    int lane = threadIdx.x & 31;
    if (warp > GLYPH_DIM) return;

    const float4* wr = (const float4*)(W_ih + lane * EMB_DIM);
    const float4* er = (const float4*)(emb + (size_t)warp * EMB_DIM);
    float4 w0 = __ldg(&wr[0]), w1 = __ldg(&wr[1]), w2 = __ldg(&wr[2]),
           w3 = __ldg(&wr[3]), w4 = __ldg(&wr[4]);
    float4 e0 = __ldg(&er[0]), e1 = __ldg(&er[1]), e2 = __ldg(&er[2]),
           e3 = __ldg(&er[3]), e4 = __ldg(&er[4]);

    float acc = __ldg(&b_ih[lane]) + __ldg(&b_hh[lane]);
    acc += w0.x*e0.x + w0.y*e0.y + w0.z*e0.z + w0.w*e0.w;
    acc += w1.x*e1.x + w1.y*e1.y + w1.z*e1.z + w1.w*e1.w;
    acc += w2.x*e2.x + w2.y*e2.y + w2.z*e2.z + w2.w*e2.w;
    acc += w3.x*e3.x + w3.y*e3.y + w3.z*e3.z + w3.w*e3.w;
    acc += w4.x*e4.x + w4.y*e4.y + w4.z*e4.z + w4.w*e4.w;

    g_utab[warp * HIDDEN + lane] = acc;
}

// ---------------------------------------------------------------------------
// Mega kernel: one warp per sample: presence -> bitmap -> bag -> emb -> RNN
// ---------------------------------------------------------------------------
__global__ __launch_bounds__(WPB * 32) void mega_kernel(
    const int* __restrict__ chars,
    const int* __restrict__ colors,
    const float* __restrict__ emb,
    const float* __restrict__ W_hh,
    float* __restrict__ out_h,
    float* __restrict__ out_emb,
    float* __restrict__ out_bag,
    int B)
{
    __shared__ __align__(16) unsigned char presence[WPB][GLYPH_DIM]; // 16 KB
    __shared__ __align__(16) int   bagsh[WPB][MAX_LEN + 4];
    __shared__ __align__(16) float hbuf [WPB][2][HIDDEN];

    const int lane = threadIdx.x & 31;
    const int w    = threadIdx.x >> 5;
    const int sample = blockIdx.x * WPB + w;
    if (sample >= B) return;

    // ---- Phase 1: zero presence ----
    {
        uint4 z = make_uint4(0u, 0u, 0u, 0u);
        uint4* p4 = (uint4*)presence[w];
#pragma unroll
        for (int i = 0; i < 8; i++) p4[lane + i * 32] = z;
    }
    __syncwarp();

    // ---- Phase 2: mark presence (deep unroll for MLP) ----
    {
        const size_t base = (size_t)sample * HW;
        const int* cp = chars + base;
        const int* kp = colors + base;
#pragma unroll 8
        for (int i = lane; i < HW; i += 32) {
            int id = (__ldg(&cp[i]) << 4) + __ldg(&kp[i]);
            presence[w][id] = 1;
        }
    }
    __syncwarp();

    // ---- Phase 3: pack to bitmap words, count, scan ----
    unsigned mw[4];
    int      cnt[4];
    {
        const uint4* pq = (const uint4*)presence[w];
#pragma unroll
        for (int m = 0; m < 4; m++) {
            uint4 A  = pq[64 * m + 2 * lane];
            uint4 Bv = pq[64 * m + 2 * lane + 1];
            unsigned n0 = ((A.x  * 0x01020408u) >> 24) & 0xFu;
            unsigned n1 = ((A.y  * 0x01020408u) >> 24) & 0xFu;
            unsigned n2 = ((A.z  * 0x01020408u) >> 24) & 0xFu;
            unsigned n3 = ((A.w  * 0x01020408u) >> 24) & 0xFu;
            unsigned n4 = ((Bv.x * 0x01020408u) >> 24) & 0xFu;
            unsigned n5 = ((Bv.y * 0x01020408u) >> 24) & 0xFu;
            unsigned n6 = ((Bv.z * 0x01020408u) >> 24) & 0xFu;
            unsigned n7 = ((Bv.w * 0x01020408u) >> 24) & 0xFu;
            unsigned word = n0 | (n1 << 4) | (n2 << 8) | (n3 << 12)
                          | (n4 << 16) | (n5 << 20) | (n6 << 24) | (n7 << 28);
            mw[m] = word;
            cnt[m] = __popc(word);
        }
    }

    int off[4];
    int runbase = 0;
#pragma unroll
    for (int m = 0; m < 4; m++) {
        int inc = cnt[m];
#pragma unroll
        for (int d = 1; d < 32; d <<= 1) {
            int n = __shfl_up_sync(0xffffffffu, inc, d);
            if (lane >= d) inc += n;
        }
        off[m] = runbase + inc - cnt[m];
        runbase += __shfl_sync(0xffffffffu, inc, 31);
    }
    const int total = runbase;
    const int steps = total < MAX_LEN ? total : MAX_LEN;

    // ---- Phase 4: emit ascending ids, pad with PAD_IDX ----
#pragma unroll
    for (int m = 0; m < 4; m++) {
        unsigned mm = mw[m];
        int o = off[m];
        int base = 1024 * m + 32 * lane;
        while (mm && o < MAX_LEN) {
            int b = __ffs(mm) - 1;
            bagsh[w][o++] = base + b;
            mm &= mm - 1;
        }
    }
#pragma unroll
    for (int i = lane; i < MAX_LEN; i += 32)
        if (i >= total) bagsh[w][i] = PAD_IDX;
    __syncwarp();

    // ---- Phase 5: outputs ----
    if (lane < 16) {
        float4 bf;
        bf.x = (float)bagsh[w][lane * 4 + 0];
        bf.y = (float)bagsh[w][lane * 4 + 1];
        bf.z = (float)bagsh[w][lane * 4 + 2];
        bf.w = (float)bagsh[w][lane * 4 + 3];
        ((float4*)(out_bag + (size_t)sample * MAX_LEN))[lane] = bf;
    }
    {
        float* dstbase = out_emb + (size_t)sample * (MAX_LEN * EMB_DIM);
#pragma unroll
        for (int rr = 0; rr < 2; rr++) {
            int r = 2 * lane + rr;
            int g = bagsh[w][r];
            const float4* src = (const float4*)(emb + (size_t)g * EMB_DIM);
            float4* dst = (float4*)(dstbase + r * EMB_DIM);
#pragma unroll
            for (int k = 0; k < 5; k++) dst[k] = __ldg(&src[k]);
        }
    }

    // ---- Phase 6: RNN (fixed 64 steps, predicated freeze, depth-4 u ring) ----
    unsigned long long w2[16];
    {
        const unsigned long long* wp = (const unsigned long long*)(W_hh + lane * HIDDEN);
#pragma unroll
        for (int j = 0; j < 16; j++) w2[j] = __ldg(&wp[j]);
    }

    hbuf[w][0][lane] = 0.f;
    float h = 0.f;
    int buf = 0;
    __syncwarp();

    float uring[4];
#pragma unroll
    for (int k = 0; k < 4; k++) {
        int g = bagsh[w][k];
        uring[k] = __ldg(&g_utab[g * HIDDEN + lane]);
    }

#pragma unroll 4
    for (int t = 0; t < MAX_LEN; t++) {
        float u = uring[t & 3];
        {
            int tn = t + 4;
            if (tn > MAX_LEN - 1) tn = MAX_LEN - 1;
            int gn = bagsh[w][tn];
            uring[t & 3] = __ldg(&g_utab[gn * HIDDEN + lane]);
        }

        const float4* hp4 = (const float4*)&hbuf[w][buf][0];
        unsigned long long accA = 0ull, accB = 0ull, accC = 0ull, accD = 0ull;
#pragma unroll
        for (int j = 0; j < 4; j++) {
            float4 v0 = hp4[2 * j];
            float4 v1 = hp4[2 * j + 1];
            unsigned long long p0, p1, p2, p3;
            asm("mov.b64 %0, {%1,%2};" : "=l"(p0) : "f"(v0.x), "f"(v0.y));
            asm("mov.b64 %0, {%1,%2};" : "=l"(p1) : "f"(v0.z), "f"(v0.w));
            asm("mov.b64 %0, {%1,%2};" : "=l"(p2) : "f"(v1.x), "f"(v1.y));
            asm("mov.b64 %0, {%1,%2};" : "=l"(p3) : "f"(v1.z), "f"(v1.w));
            asm("fma.rn.f32x2 %0, %1, %2, %3;" : "=l"(accA) : "l"(w2[4*j+0]), "l"(p0), "l"(accA));
            asm("fma.rn.f32x2 %0, %1, %2, %3;" : "=l"(accB) : "l"(w2[4*j+1]), "l"(p1), "l"(accB));
            asm("fma.rn.f32x2 %0, %1, %2, %3;" : "=l"(accC) : "l"(w2[4*j+2]), "l"(p2), "l"(accC));
            asm("fma.rn.f32x2 %0, %1, %2, %3;" : "=l"(accD) : "l"(w2[4*j+3]), "l"(p3), "l"(accD));
        }
        asm("add.rn.f32x2 %0, %1, %2;" : "=l"(accA) : "l"(accA), "l"(accB));
        asm("add.rn.f32x2 %0, %1, %2;" : "=l"(accC) : "l"(accC), "l"(accD));
        asm("add.rn.f32x2 %0, %1, %2;" : "=l"(accA) : "l"(accA), "l"(accC));
        float a0, a1;
        asm("mov.b64 {%0,%1}, %2;" : "=f"(a0), "=f"(a1) : "l"(accA));

        float pre = u + a0 + a1;
        float hn;
        asm("tanh.approx.f32 %0, %1;" : "=f"(hn) : "f"(pre));
        h = (t < steps) ? hn : h;

        buf ^= 1;
        hbuf[w][buf][lane] = h;
        __syncwarp();
    }

    out_h[(size_t)sample * HIDDEN + lane] = h;
}

// ---------------------------------------------------------------------------
// kernel_launch
// Inputs: glyph_chars, glyph_colors, emb_table, W_ih, W_hh, b_ih, b_hh
// Output: concat(h [B,32], emb [B,64,20], bag [B,64]) float32
// ---------------------------------------------------------------------------
extern "C" void kernel_launch(void* const* d_in, const int* in_sizes, int n_in,
                              void* d_out, int out_size)
{
    const int*   chars  = (const int*)  d_in[0];
    const int*   colors = (const int*)  d_in[1];
    const float* emb    = (const float*)d_in[2];
    const float* W_ih   = (const float*)d_in[3];
    const float* W_hh   = (const float*)d_in[4];
    const float* b_ih   = (const float*)d_in[5];
    const float* b_hh   = (const float*)d_in[6];

    const int B = in_sizes[0] / HW;

    float* out = (float*)d_out;
    const long long nh   = (long long)B * HIDDEN;
    const long long nemb = (long long)B * MAX_LEN * EMB_DIM;

    float* out_h   = out;
    float* out_emb = out + nh;
    float* out_bag = out + nh + nemb;

    {
        int warps  = GLYPH_DIM + 1;
        int blocks = (warps * 32 + 255) / 256;
        utab_kernel<<<blocks, 256>>>(emb, W_ih, b_ih, b_hh);
    }
    {
        int blocks = (B + WPB - 1) / WPB;
        mega_kernel<<<blocks, WPB * 32>>>(chars, colors, emb, W_hh,
                                          out_h, out_emb, out_bag, B);
    }
}

// round 4
// speedup vs baseline: 1.1092x; 1.1092x over previous
#include <cuda_runtime.h>
#include <cuda_bf16.h>
#include <cstdint>

#define GLYPH_DIM 4096
#define PAD_IDX   4096
#define EMB_DIM   20
#define HIDDEN    32
#define MAX_LEN   64
#define HW        1659        // 21 * 79
#define WPB       4           // warps (samples) per block

// ---------------------------------------------------------------------------
// Device scratch
// ---------------------------------------------------------------------------
__device__ float g_utab[(GLYPH_DIM + 1) * HIDDEN];

// ---------------------------------------------------------------------------
// K0: u_table[g][i] = W_ih[i] . emb[g] + b_ih[i] + b_hh[i]   (4097 x 32)
// ---------------------------------------------------------------------------
__global__ void utab_kernel(const float* __restrict__ emb,
                            const float* __restrict__ W_ih,
                            const float* __restrict__ b_ih,
                            const float* __restrict__ b_hh)
{
    int warp = (blockIdx.x * blockDim.x + threadIdx.x) >> 5;
    int lane = threadIdx.x & 31;
    if (warp > GLYPH_DIM) return;

    const float4* wr = (const float4*)(W_ih + lane * EMB_DIM);
    const float4* er = (const float4*)(emb + (size_t)warp * EMB_DIM);
    float4 w0 = __ldg(&wr[0]), w1 = __ldg(&wr[1]), w2 = __ldg(&wr[2]),
           w3 = __ldg(&wr[3]), w4 = __ldg(&wr[4]);
    float4 e0 = __ldg(&er[0]), e1 = __ldg(&er[1]), e2 = __ldg(&er[2]),
           e3 = __ldg(&er[3]), e4 = __ldg(&er[4]);

    float acc = __ldg(&b_ih[lane]) + __ldg(&b_hh[lane]);
    acc += w0.x*e0.x + w0.y*e0.y + w0.z*e0.z + w0.w*e0.w;
    acc += w1.x*e1.x + w1.y*e1.y + w1.z*e1.z + w1.w*e1.w;
    acc += w2.x*e2.x + w2.y*e2.y + w2.z*e2.z + w2.w*e2.w;
    acc += w3.x*e3.x + w3.y*e3.y + w3.z*e3.z + w3.w*e3.w;
    acc += w4.x*e4.x + w4.y*e4.y + w4.z*e4.z + w4.w*e4.w;

    g_utab[warp * HIDDEN + lane] = acc;
}

// ---------------------------------------------------------------------------
// Mega kernel: one warp per sample: presence -> bitmap -> bag -> emb -> RNN
// ---------------------------------------------------------------------------
__global__ __launch_bounds__(WPB * 32) void mega_kernel(
    const int* __restrict__ chars,
    const int* __restrict__ colors,
    const float* __restrict__ emb,
    const float* __restrict__ W_hh,
    float* __restrict__ out_h,
    float* __restrict__ out_emb,
    float* __restrict__ out_bag,
    int B)
{
    __shared__ __align__(16) unsigned char presence[WPB][GLYPH_DIM]; // 16 KB
    __shared__ __align__(16) int   bagsh[WPB][MAX_LEN + 4];
    __shared__ __align__(16) float hbuf [WPB][2][HIDDEN];

    const int lane = threadIdx.x & 31;
    const int w    = threadIdx.x >> 5;
    const int sample = blockIdx.x * WPB + w;
    if (sample >= B) return;

    // ---- Phase 1: zero presence ----
    {
        uint4 z = make_uint4(0u, 0u, 0u, 0u);
        uint4* p4 = (uint4*)presence[w];
#pragma unroll
        for (int i = 0; i < 8; i++) p4[lane + i * 32] = z;
    }
    __syncwarp();

    // ---- Phase 2: mark presence (deep unroll for MLP) ----
    {
        const size_t base = (size_t)sample * HW;
        const int* cp = chars + base;
        const int* kp = colors + base;
#pragma unroll 16
        for (int i = lane; i < HW; i += 32) {
            int id = (__ldg(&cp[i]) << 4) + __ldg(&kp[i]);
            presence[w][id] = 1;
        }
    }
    __syncwarp();

    // ---- Phase 3: pack to bitmap words, count, scan ----
    unsigned mw[4];
    int      cnt[4];
    {
        const uint4* pq = (const uint4*)presence[w];
#pragma unroll
        for (int m = 0; m < 4; m++) {
            uint4 A  = pq[64 * m + 2 * lane];
            uint4 Bv = pq[64 * m + 2 * lane + 1];
            unsigned n0 = ((A.x  * 0x01020408u) >> 24) & 0xFu;
            unsigned n1 = ((A.y  * 0x01020408u) >> 24) & 0xFu;
            unsigned n2 = ((A.z  * 0x01020408u) >> 24) & 0xFu;
            unsigned n3 = ((A.w  * 0x01020408u) >> 24) & 0xFu;
            unsigned n4 = ((Bv.x * 0x01020408u) >> 24) & 0xFu;
            unsigned n5 = ((Bv.y * 0x01020408u) >> 24) & 0xFu;
            unsigned n6 = ((Bv.z * 0x01020408u) >> 24) & 0xFu;
            unsigned n7 = ((Bv.w * 0x01020408u) >> 24) & 0xFu;
            unsigned word = n0 | (n1 << 4) | (n2 << 8) | (n3 << 12)
                          | (n4 << 16) | (n5 << 20) | (n6 << 24) | (n7 << 28);
            mw[m] = word;
            cnt[m] = __popc(word);
        }
    }

    int off[4];
    int runbase = 0;
#pragma unroll
    for (int m = 0; m < 4; m++) {
        int inc = cnt[m];
#pragma unroll
        for (int d = 1; d < 32; d <<= 1) {
            int n = __shfl_up_sync(0xffffffffu, inc, d);
            if (lane >= d) inc += n;
        }
        off[m] = runbase + inc - cnt[m];
        runbase += __shfl_sync(0xffffffffu, inc, 31);
    }
    const int total = runbase;
    const int steps = total < MAX_LEN ? total : MAX_LEN;

    // ---- Phase 4: emit ascending ids, pad with PAD_IDX ----
#pragma unroll
    for (int m = 0; m < 4; m++) {
        unsigned mm = mw[m];
        int o = off[m];
        int base = 1024 * m + 32 * lane;
        while (mm && o < MAX_LEN) {
            int b = __ffs(mm) - 1;
            bagsh[w][o++] = base + b;
            mm &= mm - 1;
        }
    }
#pragma unroll
    for (int i = lane; i < MAX_LEN; i += 32)
        if (i >= total) bagsh[w][i] = PAD_IDX;
    __syncwarp();

    // ---- Phase 5a: bag output (coalesced float4) ----
    if (lane < 16) {
        float4 bf;
        bf.x = (float)bagsh[w][lane * 4 + 0];
        bf.y = (float)bagsh[w][lane * 4 + 1];
        bf.z = (float)bagsh[w][lane * 4 + 2];
        bf.w = (float)bagsh[w][lane * 4 + 3];
        ((float4*)(out_bag + (size_t)sample * MAX_LEN))[lane] = bf;
    }

    // ---- Phase 5b: emb gather, mapped over the CONTIGUOUS dst ----
    // dst block = 320 float4; 5 float4 per row exactly, so e4 -> (row=e4/5,
    // k=e4%5) never splits a row. Stores fully coalesced; loads hit ~7 rows.
    {
        float4* dst4 = (float4*)(out_emb + (size_t)sample * (MAX_LEN * EMB_DIM));
        const float4* esrc = (const float4*)emb;
#pragma unroll
        for (int it = 0; it < 10; it++) {
            int e4 = it * 32 + lane;          // 0..319
            int r  = e4 / 5;
            int k  = e4 - r * 5;
            int g  = bagsh[w][r];
            dst4[e4] = __ldg(&esrc[(size_t)g * 5 + k]);
        }
    }

    // ---- Phase 6: RNN (fixed 64 steps, predicated freeze, depth-4 u ring) ----
    unsigned long long w2[16];
    {
        const unsigned long long* wp = (const unsigned long long*)(W_hh + lane * HIDDEN);
#pragma unroll
        for (int j = 0; j < 16; j++) w2[j] = __ldg(&wp[j]);
    }

    hbuf[w][0][lane] = 0.f;
    float h = 0.f;
    int buf = 0;
    __syncwarp();

    float uring[4];
#pragma unroll
    for (int k = 0; k < 4; k++) {
        int g = bagsh[w][k];
        uring[k] = __ldg(&g_utab[g * HIDDEN + lane]);
    }

#pragma unroll 4
    for (int t = 0; t < MAX_LEN; t++) {
        float u = uring[t & 3];
        {
            int tn = t + 4;
            if (tn > MAX_LEN - 1) tn = MAX_LEN - 1;
            int gn = bagsh[w][tn];
            uring[t & 3] = __ldg(&g_utab[gn * HIDDEN + lane]);
        }

        const float4* hp4 = (const float4*)&hbuf[w][buf][0];
        unsigned long long accA = 0ull, accB = 0ull, accC = 0ull, accD = 0ull;
#pragma unroll
        for (int j = 0; j < 4; j++) {
            float4 v0 = hp4[2 * j];
            float4 v1 = hp4[2 * j + 1];
            unsigned long long p0, p1, p2, p3;
            asm("mov.b64 %0, {%1,%2};" : "=l"(p0) : "f"(v0.x), "f"(v0.y));
            asm("mov.b64 %0, {%1,%2};" : "=l"(p1) : "f"(v0.z), "f"(v0.w));
            asm("mov.b64 %0, {%1,%2};" : "=l"(p2) : "f"(v1.x), "f"(v1.y));
            asm("mov.b64 %0, {%1,%2};" : "=l"(p3) : "f"(v1.z), "f"(v1.w));
            asm("fma.rn.f32x2 %0, %1, %2, %3;" : "=l"(accA) : "l"(w2[4*j+0]), "l"(p0), "l"(accA));
            asm("fma.rn.f32x2 %0, %1, %2, %3;" : "=l"(accB) : "l"(w2[4*j+1]), "l"(p1), "l"(accB));
            asm("fma.rn.f32x2 %0, %1, %2, %3;" : "=l"(accC) : "l"(w2[4*j+2]), "l"(p2), "l"(accC));
            asm("fma.rn.f32x2 %0, %1, %2, %3;" : "=l"(accD) : "l"(w2[4*j+3]), "l"(p3), "l"(accD));
        }
        asm("add.rn.f32x2 %0, %1, %2;" : "=l"(accA) : "l"(accA), "l"(accB));
        asm("add.rn.f32x2 %0, %1, %2;" : "=l"(accC) : "l"(accC), "l"(accD));
        asm("add.rn.f32x2 %0, %1, %2;" : "=l"(accA) : "l"(accA), "l"(accC));
        float a0, a1;
        asm("mov.b64 {%0,%1}, %2;" : "=f"(a0), "=f"(a1) : "l"(accA));

        float pre = u + a0 + a1;
        float hn;
        asm("tanh.approx.f32 %0, %1;" : "=f"(hn) : "f"(pre));
        h = (t < steps) ? hn : h;

        buf ^= 1;
        hbuf[w][buf][lane] = h;
        __syncwarp();
    }

    out_h[(size_t)sample * HIDDEN + lane] = h;
}

// ---------------------------------------------------------------------------
// kernel_launch
// Inputs: glyph_chars, glyph_colors, emb_table, W_ih, W_hh, b_ih, b_hh
// Output: concat(h [B,32], emb [B,64,20], bag [B,64]) float32
// ---------------------------------------------------------------------------
extern "C" void kernel_launch(void* const* d_in, const int* in_sizes, int n_in,
                              void* d_out, int out_size)
{
    const int*   chars  = (const int*)  d_in[0];
    const int*   colors = (const int*)  d_in[1];
    const float* emb    = (const float*)d_in[2];
    const float* W_ih   = (const float*)d_in[3];
    const float* W_hh   = (const float*)d_in[4];
    const float* b_ih   = (const float*)d_in[5];
    const float* b_hh   = (const float*)d_in[6];

    const int B = in_sizes[0] / HW;

    float* out = (float*)d_out;
    const long long nh   = (long long)B * HIDDEN;
    const long long nemb = (long long)B * MAX_LEN * EMB_DIM;

    float* out_h   = out;
    float* out_emb = out + nh;
    float* out_bag = out + nh + nemb;

    {
        int warps  = GLYPH_DIM + 1;
        int blocks = (warps * 32 + 255) / 256;
        utab_kernel<<<blocks, 256>>>(emb, W_ih, b_ih, b_hh);
    }
    {
        int blocks = (B + WPB - 1) / WPB;
        mega_kernel<<<blocks, WPB * 32>>>(chars, colors, emb, W_hh,
                                          out_h, out_emb, out_bag, B);
    }
}

// round 5
// speedup vs baseline: 1.1955x; 1.0778x over previous
#include <cuda_runtime.h>
#include <cuda_bf16.h>
#include <cstdint>

#define GLYPH_DIM 4096
#define PAD_IDX   4096
#define EMB_DIM   20
#define HIDDEN    32
#define MAX_LEN   64
#define HW        1659        // 21 * 79
#define WPB       4           // warps (samples) per block

// ---------------------------------------------------------------------------
// Device scratch
// ---------------------------------------------------------------------------
__device__ float g_utab[(GLYPH_DIM + 1) * HIDDEN];

// ---------------------------------------------------------------------------
// K0: u_table[g][i] = W_ih[i] . emb[g] + b_ih[i] + b_hh[i]   (4097 x 32)
// ---------------------------------------------------------------------------
__global__ void utab_kernel(const float* __restrict__ emb,
                            const float* __restrict__ W_ih,
                            const float* __restrict__ b_ih,
                            const float* __restrict__ b_hh)
{
    int warp = (blockIdx.x * blockDim.x + threadIdx.x) >> 5;
    int lane = threadIdx.x & 31;
    if (warp > GLYPH_DIM) return;

    const float4* wr = (const float4*)(W_ih + lane * EMB_DIM);
    const float4* er = (const float4*)(emb + (size_t)warp * EMB_DIM);
    float4 w0 = __ldg(&wr[0]), w1 = __ldg(&wr[1]), w2 = __ldg(&wr[2]),
           w3 = __ldg(&wr[3]), w4 = __ldg(&wr[4]);
    float4 e0 = __ldg(&er[0]), e1 = __ldg(&er[1]), e2 = __ldg(&er[2]),
           e3 = __ldg(&er[3]), e4 = __ldg(&er[4]);

    float acc = __ldg(&b_ih[lane]) + __ldg(&b_hh[lane]);
    acc += w0.x*e0.x + w0.y*e0.y + w0.z*e0.z + w0.w*e0.w;
    acc += w1.x*e1.x + w1.y*e1.y + w1.z*e1.z + w1.w*e1.w;
    acc += w2.x*e2.x + w2.y*e2.y + w2.z*e2.z + w2.w*e2.w;
    acc += w3.x*e3.x + w3.y*e3.y + w3.z*e3.z + w3.w*e3.w;
    acc += w4.x*e4.x + w4.y*e4.y + w4.z*e4.z + w4.w*e4.w;

    g_utab[warp * HIDDEN + lane] = acc;
}

// ---------------------------------------------------------------------------
// Mega kernel: one warp per sample: presence -> bitmap -> bag -> emb -> RNN
// ---------------------------------------------------------------------------
__global__ __launch_bounds__(WPB * 32) void mega_kernel(
    const int* __restrict__ chars,
    const int* __restrict__ colors,
    const float* __restrict__ emb,
    const float* __restrict__ W_hh,
    float* __restrict__ out_h,
    float* __restrict__ out_emb,
    float* __restrict__ out_bag,
    int B)
{
    __shared__ __align__(16) unsigned char presence[WPB][GLYPH_DIM]; // 16 KB
    __shared__ __align__(16) int   bagsh[WPB][MAX_LEN + 4];
    __shared__ __align__(16) float hbuf [WPB][2][HIDDEN];

    const int lane = threadIdx.x & 31;
    const int w    = threadIdx.x >> 5;
    const int sample = blockIdx.x * WPB + w;
    if (sample >= B) return;

    // ---- Phase 1: zero presence ----
    {
        uint4 z = make_uint4(0u, 0u, 0u, 0u);
        uint4* p4 = (uint4*)presence[w];
#pragma unroll
        for (int i = 0; i < 8; i++) p4[lane + i * 32] = z;
    }
    __syncwarp();

    // ---- Phase 2: mark presence (int4 vectorized, alignment-safe) ----
    {
        const size_t base = (size_t)sample * HW;
        const int* cp = chars + base;
        const int* kp = colors + base;

        const int mis = (int)(base & 3);
        const int pre = (4 - mis) & 3;            // scalars to reach 16B align
        if (lane < pre) {
            int id = (__ldg(&cp[lane]) << 4) + __ldg(&kp[lane]);
            presence[w][id] = 1;
        }
        const int nv  = (HW - pre) >> 2;          // number of int4 quads
        const int rem = HW - pre - (nv << 2);     // tail scalars

        const int4* cp4 = (const int4*)(cp + pre);
        const int4* kp4 = (const int4*)(kp + pre);
#pragma unroll 4
        for (int i = lane; i < nv; i += 32) {
            int4 c = __ldg(&cp4[i]);
            int4 k = __ldg(&kp4[i]);
            presence[w][(c.x << 4) + k.x] = 1;
            presence[w][(c.y << 4) + k.y] = 1;
            presence[w][(c.z << 4) + k.z] = 1;
            presence[w][(c.w << 4) + k.w] = 1;
        }
        if (lane < rem) {
            int idx = pre + (nv << 2) + lane;
            int id = (__ldg(&cp[idx]) << 4) + __ldg(&kp[idx]);
            presence[w][id] = 1;
        }
    }
    __syncwarp();

    // ---- Phase 3: pack to bitmap words, count, scan ----
    unsigned mw[4];
    int      cnt[4];
    {
        const uint4* pq = (const uint4*)presence[w];
#pragma unroll
        for (int m = 0; m < 4; m++) {
            uint4 A  = pq[64 * m + 2 * lane];
            uint4 Bv = pq[64 * m + 2 * lane + 1];
            unsigned n0 = ((A.x  * 0x01020408u) >> 24) & 0xFu;
            unsigned n1 = ((A.y  * 0x01020408u) >> 24) & 0xFu;
            unsigned n2 = ((A.z  * 0x01020408u) >> 24) & 0xFu;
            unsigned n3 = ((A.w  * 0x01020408u) >> 24) & 0xFu;
            unsigned n4 = ((Bv.x * 0x01020408u) >> 24) & 0xFu;
            unsigned n5 = ((Bv.y * 0x01020408u) >> 24) & 0xFu;
            unsigned n6 = ((Bv.z * 0x01020408u) >> 24) & 0xFu;
            unsigned n7 = ((Bv.w * 0x01020408u) >> 24) & 0xFu;
            unsigned word = n0 | (n1 << 4) | (n2 << 8) | (n3 << 12)
                          | (n4 << 16) | (n5 << 20) | (n6 << 24) | (n7 << 28);
            mw[m] = word;
            cnt[m] = __popc(word);
        }
    }

    int off[4];
    int runbase = 0;
#pragma unroll
    for (int m = 0; m < 4; m++) {
        int inc = cnt[m];
#pragma unroll
        for (int d = 1; d < 32; d <<= 1) {
            int n = __shfl_up_sync(0xffffffffu, inc, d);
            if (lane >= d) inc += n;
        }
        off[m] = runbase + inc - cnt[m];
        runbase += __shfl_sync(0xffffffffu, inc, 31);
    }
    const int total = runbase;
    const int steps = total < MAX_LEN ? total : MAX_LEN;

    // ---- Phase 4: emit ascending ids, pad with PAD_IDX ----
#pragma unroll
    for (int m = 0; m < 4; m++) {
        unsigned mm = mw[m];
        int o = off[m];
        int base = 1024 * m + 32 * lane;
        while (mm && o < MAX_LEN) {
            int b = __ffs(mm) - 1;
            bagsh[w][o++] = base + b;
            mm &= mm - 1;
        }
    }
#pragma unroll
    for (int i = lane; i < MAX_LEN; i += 32)
        if (i >= total) bagsh[w][i] = PAD_IDX;
    __syncwarp();

    // ---- Phase 5a: bag output (coalesced float4) ----
    if (lane < 16) {
        float4 bf;
        bf.x = (float)bagsh[w][lane * 4 + 0];
        bf.y = (float)bagsh[w][lane * 4 + 1];
        bf.z = (float)bagsh[w][lane * 4 + 2];
        bf.w = (float)bagsh[w][lane * 4 + 3];
        ((float4*)(out_bag + (size_t)sample * MAX_LEN))[lane] = bf;
    }

    // ---- Phase 5b: emb gather over the contiguous dst (coalesced stores) ----
    {
        float4* dst4 = (float4*)(out_emb + (size_t)sample * (MAX_LEN * EMB_DIM));
        const float4* esrc = (const float4*)emb;
#pragma unroll
        for (int it = 0; it < 10; it++) {
            int e4 = it * 32 + lane;          // 0..319
            int r  = e4 / 5;
            int k  = e4 - r * 5;
            int g  = bagsh[w][r];
            dst4[e4] = __ldg(&esrc[(size_t)g * 5 + k]);
        }
    }

    // ---- Phase 6: RNN (fixed 64 steps, predicated freeze, depth-4 u ring) ----
    unsigned long long w2[16];
    {
        const unsigned long long* wp = (const unsigned long long*)(W_hh + lane * HIDDEN);
#pragma unroll
        for (int j = 0; j < 16; j++) w2[j] = __ldg(&wp[j]);
    }

    hbuf[w][0][lane] = 0.f;
    float h = 0.f;
    int buf = 0;
    __syncwarp();

    float uring[4];
#pragma unroll
    for (int k = 0; k < 4; k++) {
        int g = bagsh[w][k];
        uring[k] = __ldg(&g_utab[g * HIDDEN + lane]);
    }

#pragma unroll 4
    for (int t = 0; t < MAX_LEN; t++) {
        float u = uring[t & 3];
        {
            int tn = t + 4;
            if (tn > MAX_LEN - 1) tn = MAX_LEN - 1;
            int gn = bagsh[w][tn];
            uring[t & 3] = __ldg(&g_utab[gn * HIDDEN + lane]);
        }

        // h vector as 64-bit pairs directly (no float4 -> b64 repacking)
        const ulonglong2* hp2 = (const ulonglong2*)&hbuf[w][buf][0];
        unsigned long long accA = 0ull, accB = 0ull, accC = 0ull, accD = 0ull;
#pragma unroll
        for (int j = 0; j < 4; j++) {
            ulonglong2 q0 = hp2[2 * j];
            ulonglong2 q1 = hp2[2 * j + 1];
            asm("fma.rn.f32x2 %0, %1, %2, %3;" : "=l"(accA) : "l"(w2[4*j+0]), "l"(q0.x), "l"(accA));
            asm("fma.rn.f32x2 %0, %1, %2, %3;" : "=l"(accB) : "l"(w2[4*j+1]), "l"(q0.y), "l"(accB));
            asm("fma.rn.f32x2 %0, %1, %2, %3;" : "=l"(accC) : "l"(w2[4*j+2]), "l"(q1.x), "l"(accC));
            asm("fma.rn.f32x2 %0, %1, %2, %3;" : "=l"(accD) : "l"(w2[4*j+3]), "l"(q1.y), "l"(accD));
        }
        asm("add.rn.f32x2 %0, %1, %2;" : "=l"(accA) : "l"(accA), "l"(accB));
        asm("add.rn.f32x2 %0, %1, %2;" : "=l"(accC) : "l"(accC), "l"(accD));
        asm("add.rn.f32x2 %0, %1, %2;" : "=l"(accA) : "l"(accA), "l"(accC));
        float a0, a1;
        asm("mov.b64 {%0,%1}, %2;" : "=f"(a0), "=f"(a1) : "l"(accA));

        float pre = u + a0 + a1;
        float hn;
        asm("tanh.approx.f32 %0, %1;" : "=f"(hn) : "f"(pre));
        h = (t < steps) ? hn : h;

        buf ^= 1;
        hbuf[w][buf][lane] = h;
        __syncwarp();
    }

    out_h[(size_t)sample * HIDDEN + lane] = h;
}

// ---------------------------------------------------------------------------
// kernel_launch
// Inputs: glyph_chars, glyph_colors, emb_table, W_ih, W_hh, b_ih, b_hh
// Output: concat(h [B,32], emb [B,64,20], bag [B,64]) float32
// ---------------------------------------------------------------------------
extern "C" void kernel_launch(void* const* d_in, const int* in_sizes, int n_in,
                              void* d_out, int out_size)
{
    const int*   chars  = (const int*)  d_in[0];
    const int*   colors = (const int*)  d_in[1];
    const float* emb    = (const float*)d_in[2];
    const float* W_ih   = (const float*)d_in[3];
    const float* W_hh   = (const float*)d_in[4];
    const float* b_ih   = (const float*)d_in[5];
    const float* b_hh   = (const float*)d_in[6];

    const int B = in_sizes[0] / HW;

    float* out = (float*)d_out;
    const long long nh   = (long long)B * HIDDEN;
    const long long nemb = (long long)B * MAX_LEN * EMB_DIM;

    float* out_h   = out;
    float* out_emb = out + nh;
    float* out_bag = out + nh + nemb;

    {
        int warps  = GLYPH_DIM + 1;
        int blocks = (warps * 32 + 255) / 256;
        utab_kernel<<<blocks, 256>>>(emb, W_ih, b_ih, b_hh);
    }
    {
        int blocks = (B + WPB - 1) / WPB;
        mega_kernel<<<blocks, WPB * 32>>>(chars, colors, emb, W_hh,
                                          out_h, out_emb, out_bag, B);
    }
}